// round 16
// baseline (speedup 1.0000x reference)
#include <cuda_runtime.h>
#include <cstdint>

// ---------------- problem constants ----------------
#define D_DIM  512
#define HID    513
#define P_CTX  8192
#define KTEST  2048
#define LDEPTH 8

#define NCTA    296          // 2 CTAs per SM
#define NT      9            // 64-tiles per matrix dim (576 = 9*64)
#define NTILES  81
#define CH      32           // K floats per chunk
#define KCHUNKS 17           // K = 544 (covers 513)
#define PSTRIDE 4096         // floats per piece (64x64 tile)
#define NPIECE  5            // max pieces per tile
#define TSTRIDE (NPIECE*PSTRIDE)
#define MATSZ   (NTILES*TSTRIDE)

#define SPAIR 45
#define SPC   8
#define SCALE_A (1.0f/65536.0f)

// dynamic smem: 4 tile buffers (2xA, 2xB) of 32x68 floats + np tables
#define SM_BUF   2176
#define SM_NP    8704
#define SMEM_BYTES ((8704 + 32) * 4)

// matrix ids
#define mWXA 0
#define mWQT 1
#define mWKT 2
#define mWVP 3
#define mS   4
#define mF   5
#define mT   6
#define mT2  7
#define mG   8
#define mA0  9
#define NMAT 17

#define NSTEPS 33

// ---------------- device storage ----------------
__device__ float g_M[NMAT][MATSZ];
__device__ float g_Spc[SPAIR*SPC*PSTRIDE];
__device__ float g_u[2][544];
__device__ float g_dv[544];
__device__ unsigned g_barCnt = 0;
__device__ unsigned g_barGen = 0;

// ---------------- static schedules ----------------
// GEMM: 81*17 = 1377 chunks over 296 CTAs: CTA<193 get 5, rest 4
__device__ __forceinline__ int gsch_start(int c){ return c < 193 ? 5*c : 4*c + 193; }
__device__ __forceinline__ int gsch_len  (int c){ return c < 193 ? 5 : 4; }
__device__ __forceinline__ int gsch_cta  (int g){ return g < 965 ? g/5 : 193 + (g-965)/4; }
__device__ __forceinline__ int np_gemm   (int t){ return gsch_cta(t*17+16) - gsch_cta(t*17) + 1; }
// syrk: 45*256 = 11520 chunks over 296 CTAs: CTA<272 get 39, rest 38
__device__ __forceinline__ int ssch_start(int c){ return c < 272 ? 39*c : 38*c + 272; }
__device__ __forceinline__ int ssch_len  (int c){ return c < 272 ? 39 : 38; }
__device__ __forceinline__ int ssch_cta  (int g){ return g < 10608 ? g/39 : 272 + (g-10608)/38; }
__device__ __forceinline__ int np_syrk   (int q){ return ssch_cta(q*256+255) - ssch_cta(q*256) + 1; }

// ------- grid barrier: flat release/acquire, gpu scope ----
__device__ __forceinline__ void gsync() {
    __syncthreads();
    if (threadIdx.x == 0) {
        unsigned long long cntA, genA;
        asm("cvta.global.u64 %0, %1;" : "=l"(cntA) : "l"(&g_barCnt));
        asm("cvta.global.u64 %0, %1;" : "=l"(genA) : "l"(&g_barGen));
        unsigned gen;
        asm volatile("ld.acquire.gpu.global.u32 %0, [%1];" : "=r"(gen) : "l"(genA));
        unsigned prev;
        asm volatile("atom.release.gpu.global.add.u32 %0, [%1], 1;"
                     : "=r"(prev) : "l"(cntA));
        if (prev == NCTA - 1) {
            asm volatile("st.relaxed.gpu.global.u32 [%0], %1;" :: "l"(cntA), "r"(0u));
            asm volatile("st.release.gpu.global.u32 [%0], %1;" :: "l"(genA), "r"(gen + 1u));
        } else {
            unsigned g2;
            do {
                __nanosleep(32);
                asm volatile("ld.acquire.gpu.global.u32 %0, [%1];" : "=r"(g2) : "l"(genA));
            } while (g2 == gen);
        }
    }
    __syncthreads();
}

// ---------------- piece-summed float4 read ----------------
__device__ __forceinline__ float4 rd4(const float* base, int tile, int np, int off) {
    const float* p = base + (size_t)tile * TSTRIDE + off;
    float4 v = *(const float4*)p;
    #pragma unroll
    for (int q = 1; q < NPIECE; q++) {
        if (q < np) {
            float4 w = *(const float4*)(p + q * PSTRIDE);
            v.x += w.x; v.y += w.y; v.z += w.z; v.w += w.w;
        }
    }
    return v;
}

// ---------------- one GEMM chunk-job ----------------
__device__ __forceinline__ void gemm_job(
    const float* Ab, int multA, const float* Bb, int multB,
    const float* Dmb, int multD, float* Cb,
    int tile, int a0, int nc, int piece, float alpha, int mode1)
{
    extern __shared__ float s_dyn[];
    int* s_np = (int*)(s_dyn + SM_NP);
    const int tid = threadIdx.x;
    const int am = tid >> 2, ak = (tid & 3) * 4;   // covers k 0..15; +16 second half
    const int tx = tid & 15, ty = tid >> 4;
    const int tm = tile / NT, tn = tile % NT;

    if (tid < 9)        s_np[tid] = multA ? np_gemm(tm * NT + tid) : 1;
    else if (tid < 18)  s_np[tid] = multB ? np_gemm(tn * NT + (tid - 9)) : 1;
    else if (tid == 18) s_np[18]  = multD ? np_gemm(tile) : 1;
    __syncthreads();

    float4 va0, va1, vb0, vb1;
    auto ldg = [&](int ch) {
        const int k0 = (a0 + ch) * CH;            // 32-aligned, within one 64-tile
        const int tk = k0 >> 6;
        const int off = am * 64 + (k0 & 63) + ak;
        const int npa = s_np[tk], npb = s_np[9 + tk];
        va0 = rd4(Ab, tm * NT + tk, npa, off);
        va1 = rd4(Ab, tm * NT + tk, npa, off + 16);
        vb0 = rd4(Bb, tn * NT + tk, npb, off);
        vb1 = rd4(Bb, tn * NT + tk, npb, off + 16);
    };
    auto sts = [&](int buf) {
        float* A = s_dyn + buf * SM_BUF;
        float* B = s_dyn + 2 * SM_BUF + buf * SM_BUF;
        A[(ak+0)*68 + am] = va0.x; A[(ak+1)*68 + am] = va0.y;
        A[(ak+2)*68 + am] = va0.z; A[(ak+3)*68 + am] = va0.w;
        A[(ak+16)*68 + am] = va1.x; A[(ak+17)*68 + am] = va1.y;
        A[(ak+18)*68 + am] = va1.z; A[(ak+19)*68 + am] = va1.w;
        B[(ak+0)*68 + am] = vb0.x; B[(ak+1)*68 + am] = vb0.y;
        B[(ak+2)*68 + am] = vb0.z; B[(ak+3)*68 + am] = vb0.w;
        B[(ak+16)*68 + am] = vb1.x; B[(ak+17)*68 + am] = vb1.y;
        B[(ak+18)*68 + am] = vb1.z; B[(ak+19)*68 + am] = vb1.w;
    };

    float acc[4][4] = {};
    ldg(0); sts(0);
    __syncthreads();

    for (int ch = 0; ch < nc; ch++) {
        const int buf = ch & 1;
        const bool more = (ch + 1 < nc);
        if (more) ldg(ch + 1);
        const float* A = s_dyn + buf * SM_BUF;
        const float* B = s_dyn + 2 * SM_BUF + buf * SM_BUF;
        #pragma unroll
        for (int kk = 0; kk < CH; kk++) {
            float4 a4 = *(const float4*)(A + kk * 68 + ty * 4);
            float4 b4 = *(const float4*)(B + kk * 68 + tx * 4);
            float a[4] = {a4.x, a4.y, a4.z, a4.w};
            float b[4] = {b4.x, b4.y, b4.z, b4.w};
            #pragma unroll
            for (int i = 0; i < 4; i++)
                #pragma unroll
                for (int j = 0; j < 4; j++)
                    acc[i][j] += a[i] * b[j];
        }
        if (more) {
            sts(buf ^ 1);
            __syncthreads();
        }
    }

    float* Cp = Cb + (size_t)tile * TSTRIDE + piece * PSTRIDE;
    #pragma unroll
    for (int i = 0; i < 4; i++) {
        const int row = ty * 4 + i;
        float4 v = make_float4(acc[i][0], acc[i][1], acc[i][2], acc[i][3]);
        if (!mode1) {
            v.x *= alpha; v.y *= alpha; v.z *= alpha; v.w *= alpha;
        } else if (piece == 0) {
            float4 d = rd4(Dmb, tile, s_np[18], row * 64 + tx * 4);
            v = make_float4(d.x - v.x, d.y - v.y, d.z - v.z, d.w - v.w);
        } else {
            v = make_float4(-v.x, -v.y, -v.z, -v.w);
        }
        *(float4*)(Cp + row * 64 + tx * 4) = v;
    }
    __syncthreads();
}

// ---------------- one syrk chunk-job ----------------
__device__ __forceinline__ void syrk_job(
    const float* X, const float* yv, int q, int a0, int nc, int piece)
{
    extern __shared__ float s_dyn[];
    const int tid = threadIdx.x;
    const int pl = tid >> 4, c4 = (tid & 15) * 4;   // rows pl and pl+16
    const int tx = tid & 15, ty = tid >> 4;
    int ti = 0, rem = q;
    while (rem >= NT - ti) { rem -= NT - ti; ti++; }
    const int tj = ti + rem;
    const int bm = ti * 64, bn = tj * 64;

    float4 va0, va1, vb0, vb1;
    auto aug4 = [&](int c0, int p) -> float4 {
        if (c0 < D_DIM) return *(const float4*)(X + (size_t)p * D_DIM + c0);
        float4 v = {0.f, 0.f, 0.f, 0.f};
        if (c0 == D_DIM) v.x = yv[p];
        return v;
    };
    auto ldg = [&](int ch) {
        const int p = (a0 + ch) * CH + pl;
        va0 = aug4(bm + c4, p);
        vb0 = aug4(bn + c4, p);
        va1 = aug4(bm + c4, p + 16);
        vb1 = aug4(bn + c4, p + 16);
    };
    auto sts = [&](int buf) {
        float* A = s_dyn + buf * SM_BUF;
        float* B = s_dyn + 2 * SM_BUF + buf * SM_BUF;
        *(float4*)(A + pl * 68 + c4) = va0;
        *(float4*)(B + pl * 68 + c4) = vb0;
        *(float4*)(A + (pl + 16) * 68 + c4) = va1;
        *(float4*)(B + (pl + 16) * 68 + c4) = vb1;
    };

    float acc[4][4] = {};
    ldg(0); sts(0);
    __syncthreads();
    for (int ch = 0; ch < nc; ch++) {
        const int buf = ch & 1;
        const bool more = (ch + 1 < nc);
        if (more) ldg(ch + 1);
        const float* A = s_dyn + buf * SM_BUF;
        const float* B = s_dyn + 2 * SM_BUF + buf * SM_BUF;
        #pragma unroll
        for (int kk = 0; kk < CH; kk++) {
            float4 a4 = *(const float4*)(A + kk * 68 + ty * 4);
            float4 b4 = *(const float4*)(B + kk * 68 + tx * 4);
            float a[4] = {a4.x, a4.y, a4.z, a4.w};
            float b[4] = {b4.x, b4.y, b4.z, b4.w};
            #pragma unroll
            for (int i = 0; i < 4; i++)
                #pragma unroll
                for (int j = 0; j < 4; j++)
                    acc[i][j] += a[i] * b[j];
        }
        if (more) {
            sts(buf ^ 1);
            __syncthreads();
        }
    }
    float* P = g_Spc + ((size_t)q * SPC + piece) * PSTRIDE;
    #pragma unroll
    for (int i = 0; i < 4; i++)
        *(float4*)(P + (ty * 4 + i) * 64 + tx * 4) =
            make_float4(acc[i][0], acc[i][1], acc[i][2], acc[i][3]);
    __syncthreads();
}

// ---------------- step descriptors ----------------
struct StepD { int a, b, dm, c; float alpha; };
__device__ __forceinline__ StepD get_step(int s) {
    if (s == 0) return {mWXA, mS,   -1, mT, 1.f};
    if (s == 1) return {mT,   mWXA, -1, mG, 1.f};
    if (s == 2) return {mWQT, mWKT, -1, mF, 1.f};
    const int l = (s - 3) >> 2, r = (s - 3) & 3;
    const int al = mA0 + l;
    if (r == 0) return {mF,   mG, -1, mT, 1.f};
    if (r == 1) return {mWVP, mT, -1, al, SCALE_A};
    if (r == 2) return {al,   mG, mG, mT2, 1.f};
    return {mT2, al, mT2, mG, 1.f};
}

// ================= the megakernel =================
__global__ __launch_bounds__(256, 2) void mega(
    const float* __restrict__ X,  const float* __restrict__ yv,
    const float* __restrict__ Xs, const float* __restrict__ Wx,
    const float* __restrict__ wy, const float* __restrict__ wo,
    const float* __restrict__ Wk, const float* __restrict__ Wq,
    const float* __restrict__ Wv, float* __restrict__ out)
{
    extern __shared__ float s_dyn[];
    const int tid  = threadIdx.x;
    const int cta  = blockIdx.x;
    const int gtid = cta * 256 + tid;
    const int lane = tid & 31;
    const int gw   = (cta << 3) + (tid >> 5);

    // -------- phase 0: operand conversion to tile layout --------
    for (int idx = gtid; idx < 4 * NTILES * PSTRIDE; idx += NCTA * 256) {
        const int m = idx / (NTILES * PSTRIDE);
        const int r4 = idx - m * (NTILES * PSTRIDE);
        const int t = r4 >> 12, e = r4 & 4095;
        const int r = (t / NT) * 64 + (e >> 6);
        const int cc = (t % NT) * 64 + (e & 63);
        const bool inb = (r < HID && cc < HID);
        float v = 0.f;
        if (m == 0) { if (r < HID) { if (cc < D_DIM) v = Wx[(size_t)r*D_DIM + cc];
                                     else if (cc == D_DIM) v = wy[r]; } }
        else if (m == 1) { if (inb) v = Wq[(size_t)cc*HID + r]; }
        else if (m == 2) { if (inb) v = Wk[(size_t)cc*HID + r]; }
        else             { if (inb) v = Wv[(size_t)r*HID + cc]; }
        g_M[m][(size_t)t * TSTRIDE + e] = v;
    }

    // -------- syrk --------
    {
        const int gs = ssch_start(cta), len = ssch_len(cta);
        const int t0 = gs / 256, a0 = gs % 256;
        const int n1 = (256 - a0 < len) ? (256 - a0) : len;
        syrk_job(X, yv, t0, a0, n1, cta - ssch_cta(t0 * 256));
        if (len > n1)
            syrk_job(X, yv, t0 + 1, 0, len - n1, 0);
    }
    gsync();

    // -------- S consolidation --------
    for (int idx = gtid; idx < SPAIR * PSTRIDE; idx += NCTA * 256) {
        const int q = idx >> 12, e = idx & 4095;
        const int np = np_syrk(q);
        float s = 0.f;
        for (int p = 0; p < np; p++) s += g_Spc[((size_t)q * SPC + p) * PSTRIDE + e];
        int ti = 0, rem = q;
        while (rem >= NT - ti) { rem -= NT - ti; ti++; }
        const int tj = ti + rem;
        const int m = e >> 6, n = e & 63;
        g_M[mS][(size_t)(ti * NT + tj) * TSTRIDE + e] = s;
        g_M[mS][(size_t)(tj * NT + ti) * TSTRIDE + n * 64 + m] = s;
    }
    gsync();

    // -------- 33 GEMM steps --------
    const int ggs = gsch_start(cta), glen = gsch_len(cta);
    const int jt0 = ggs / KCHUNKS, ja0 = ggs % KCHUNKS;
    const int jn1 = (KCHUNKS - ja0 < glen) ? (KCHUNKS - ja0) : glen;
    const int p1 = cta - gsch_cta(jt0 * KCHUNKS);

    for (int s = 0; s < NSTEPS; s++) {
        const StepD st = get_step(s);
        const float* Ab = g_M[st.a];
        const float* Bb = g_M[st.b];
        const float* Db = (st.dm >= 0) ? g_M[st.dm] : nullptr;
        float* Cb = g_M[st.c];
        const int mA = st.a >= mF, mB = st.b >= mF;
        const int mD = (st.dm >= 0) ? (st.dm >= mF) : 0;
        const int mode1 = (st.dm >= 0);
        gemm_job(Ab, mA, Bb, mB, Db, mD, Cb, jt0, ja0, jn1, p1, st.alpha, mode1);
        if (glen > jn1)
            gemm_job(Ab, mA, Bb, mB, Db, mD, Cb, jt0 + 1, 0, glen - jn1, 0, st.alpha, mode1);
        gsync();
    }

    // -------- u chain --------
    for (int it = 0; it < 8; it++) {
        const float* Al = g_M[mA0 + (7 - it)];
        if (gw < HID) {
            const int j = gw, tj = j >> 6, jl = j & 63;
            float sacc = 0.f;
            #pragma unroll 2
            for (int i = lane; i < HID; i += 32) {
                const int t = (i >> 6) * NT + tj;
                const int np = np_gemm(t);
                const float* p = Al + (size_t)t * TSTRIDE + (i & 63) * 64 + jl;
                float av = p[0];
                #pragma unroll
                for (int q2 = 1; q2 < NPIECE; q2++)
                    if (q2 < np) av += p[q2 * PSTRIDE];
                const float uv = (it == 0) ? wo[i] : g_u[(it - 1) & 1][i];
                sacc += av * uv;
            }
            #pragma unroll
            for (int o = 16; o; o >>= 1) sacc += __shfl_xor_sync(0xFFFFFFFFu, sacc, o);
            if (lane == 0) {
                const float uj = (it == 0) ? wo[j] : g_u[(it - 1) & 1][j];
                g_u[it & 1][j] = uj + sacc;
            }
        }
        gsync();
    }

    // -------- d = Wx^T u --------
    if (gw < D_DIM) {
        const int j = gw;
        float sacc = 0.f;
        #pragma unroll 2
        for (int i = lane; i < HID; i += 32) sacc += Wx[(size_t)i * D_DIM + j] * g_u[1][i];
        #pragma unroll
        for (int o = 16; o; o >>= 1) sacc += __shfl_xor_sync(0xFFFFFFFFu, sacc, o);
        if (lane == 0) g_dv[j] = sacc;
    }
    gsync();

    // -------- out[k] = Xs[k,:] . d --------
    for (int r = gw; r < KTEST; r += NCTA * 8) {
        const float* row = Xs + (size_t)r * D_DIM;
        float sacc = 0.f;
        #pragma unroll 4
        for (int c2 = lane; c2 < D_DIM; c2 += 32) sacc += row[c2] * g_dv[c2];
        #pragma unroll
        for (int o = 16; o; o >>= 1) sacc += __shfl_xor_sync(0xFFFFFFFFu, sacc, o);
        if (lane == 0) out[r] = sacc;
    }
}

// ---------------- host ----------------
extern "C" void kernel_launch(void* const* d_in, const int* in_sizes, int n_in,
                              void* d_out, int out_size)
{
    const float* X  = (const float*)d_in[0];
    const float* y  = (const float*)d_in[1];
    const float* Xs = (const float*)d_in[2];
    const float* Wx = (const float*)d_in[3];
    const float* wy = (const float*)d_in[4];
    const float* wo = (const float*)d_in[5];
    const float* Wk = (const float*)d_in[6];
    const float* Wq = (const float*)d_in[7];
    const float* Wv = (const float*)d_in[8];
    float* out = (float*)d_out;

    mega<<<NCTA, 256, SMEM_BYTES>>>(X, y, Xs, Wx, wy, wo, Wk, Wq, Wv, out);
}

// round 17
// speedup vs baseline: 1.1265x; 1.1265x over previous
#include <cuda_runtime.h>
#include <cstdint>

// ---------------- problem constants ----------------
#define D_DIM  512
#define HID    513
#define P_CTX  8192
#define KTEST  2048
#define LDEPTH 8

#define NCTA    296          // 2 CTAs per SM
#define NT      9            // 64-tiles per matrix dim (576 = 9*64)
#define NTILES  81
#define CH      32           // K floats per chunk
#define KCHUNKS 17           // K = 544 (covers 513)
#define PSTRIDE 4096         // floats per piece (64x64 tile)
#define NPIECE  5            // max pieces per tile
#define TSTRIDE (NPIECE*PSTRIDE)
#define MATSZ   (NTILES*TSTRIDE)

#define SPAIR 45
#define SPC   8
#define SCALE_A (1.0f/65536.0f)

// dynamic smem: 4 tile buffers (2xA, 2xB) of 32x68 floats
#define SM_BUF   2176
#define SMEM_BYTES (4 * 2176 * 4)

// matrix ids
#define mWXA 0
#define mWQT 1
#define mWKT 2
#define mWVP 3
#define mS   4
#define mF   5
#define mT   6
#define mT2  7
#define mG   8
#define mA0  9
#define NMAT 17

#define NSTEPS 33

// ---------------- device storage ----------------
__device__ float g_M[NMAT][MATSZ];
__device__ float g_Spc[SPAIR*SPC*PSTRIDE];
__device__ float g_u[2][544];
__device__ float g_dv[544];
__device__ unsigned g_barCnt = 0;
__device__ unsigned g_barGen = 0;

// ---------------- static schedules ----------------
// GEMM: 81*17 = 1377 chunks over 296 CTAs: CTA<193 get 5, rest 4
__device__ __forceinline__ int gsch_start(int c){ return c < 193 ? 5*c : 4*c + 193; }
__device__ __forceinline__ int gsch_len  (int c){ return c < 193 ? 5 : 4; }
__device__ __forceinline__ int gsch_cta  (int g){ return g < 965 ? g/5 : 193 + (g-965)/4; }
__device__ __forceinline__ int np_gemm   (int t){ return gsch_cta(t*17+16) - gsch_cta(t*17) + 1; }
// syrk: 45*256 = 11520 chunks over 296 CTAs: CTA<272 get 39, rest 38
__device__ __forceinline__ int ssch_start(int c){ return c < 272 ? 39*c : 38*c + 272; }
__device__ __forceinline__ int ssch_len  (int c){ return c < 272 ? 39 : 38; }
__device__ __forceinline__ int ssch_cta  (int g){ return g < 10608 ? g/39 : 272 + (g-10608)/38; }
__device__ __forceinline__ int np_syrk   (int q){ return ssch_cta(q*256+255) - ssch_cta(q*256) + 1; }

// ------- grid barrier: flat release/acquire, gpu scope ----
__device__ __forceinline__ void gsync() {
    __syncthreads();
    if (threadIdx.x == 0) {
        unsigned long long cntA, genA;
        asm("cvta.global.u64 %0, %1;" : "=l"(cntA) : "l"(&g_barCnt));
        asm("cvta.global.u64 %0, %1;" : "=l"(genA) : "l"(&g_barGen));
        unsigned gen;
        asm volatile("ld.acquire.gpu.global.u32 %0, [%1];" : "=r"(gen) : "l"(genA));
        unsigned prev;
        asm volatile("atom.release.gpu.global.add.u32 %0, [%1], 1;"
                     : "=r"(prev) : "l"(cntA));
        if (prev == NCTA - 1) {
            asm volatile("st.relaxed.gpu.global.u32 [%0], %1;" :: "l"(cntA), "r"(0u));
            asm volatile("st.release.gpu.global.u32 [%0], %1;" :: "l"(genA), "r"(gen + 1u));
        } else {
            unsigned g2;
            do {
                __nanosleep(32);
                asm volatile("ld.acquire.gpu.global.u32 %0, [%1];" : "=r"(g2) : "l"(genA));
            } while (g2 == gen);
        }
    }
    __syncthreads();
}

// ---------------- one GEMM chunk-job (dense np=1 operand reads) -----------
__device__ __forceinline__ void gemm_job(
    const float* Ab, const float* Bb, const float* Dmb, float* Cb,
    int tile, int a0, int nc, int piece, float alpha, int mode1)
{
    extern __shared__ float s_dyn[];
    const int tid = threadIdx.x;
    const int am = tid >> 2, ak = (tid & 3) * 4;
    const int tx = tid & 15, ty = tid >> 4;
    const int tm = tile / NT, tn = tile % NT;

    float4 va0, va1, vb0, vb1;
    auto ldg = [&](int ch) {
        const int k0 = (a0 + ch) * CH;
        const int tk = k0 >> 6;
        const int off = am * 64 + (k0 & 63) + ak;
        const float* Ap = Ab + (size_t)(tm * NT + tk) * TSTRIDE + off;
        const float* Bp = Bb + (size_t)(tn * NT + tk) * TSTRIDE + off;
        va0 = *(const float4*)(Ap);
        va1 = *(const float4*)(Ap + 16);
        vb0 = *(const float4*)(Bp);
        vb1 = *(const float4*)(Bp + 16);
    };
    auto sts = [&](int buf) {
        float* A = s_dyn + buf * SM_BUF;
        float* B = s_dyn + 2 * SM_BUF + buf * SM_BUF;
        A[(ak+0)*68 + am] = va0.x; A[(ak+1)*68 + am] = va0.y;
        A[(ak+2)*68 + am] = va0.z; A[(ak+3)*68 + am] = va0.w;
        A[(ak+16)*68 + am] = va1.x; A[(ak+17)*68 + am] = va1.y;
        A[(ak+18)*68 + am] = va1.z; A[(ak+19)*68 + am] = va1.w;
        B[(ak+0)*68 + am] = vb0.x; B[(ak+1)*68 + am] = vb0.y;
        B[(ak+2)*68 + am] = vb0.z; B[(ak+3)*68 + am] = vb0.w;
        B[(ak+16)*68 + am] = vb1.x; B[(ak+17)*68 + am] = vb1.y;
        B[(ak+18)*68 + am] = vb1.z; B[(ak+19)*68 + am] = vb1.w;
    };

    float acc[4][4] = {};
    ldg(0); sts(0);
    __syncthreads();

    for (int ch = 0; ch < nc; ch++) {
        const int buf = ch & 1;
        const bool more = (ch + 1 < nc);
        if (more) ldg(ch + 1);
        const float* A = s_dyn + buf * SM_BUF;
        const float* B = s_dyn + 2 * SM_BUF + buf * SM_BUF;
        #pragma unroll
        for (int kk = 0; kk < CH; kk++) {
            float4 a4 = *(const float4*)(A + kk * 68 + ty * 4);
            float4 b4 = *(const float4*)(B + kk * 68 + tx * 4);
            float a[4] = {a4.x, a4.y, a4.z, a4.w};
            float b[4] = {b4.x, b4.y, b4.z, b4.w};
            #pragma unroll
            for (int i = 0; i < 4; i++)
                #pragma unroll
                for (int j = 0; j < 4; j++)
                    acc[i][j] += a[i] * b[j];
        }
        if (more) {
            sts(buf ^ 1);
            __syncthreads();
        }
    }

    float* Cp = Cb + (size_t)tile * TSTRIDE + piece * PSTRIDE;
    #pragma unroll
    for (int i = 0; i < 4; i++) {
        const int row = ty * 4 + i;
        float4 v = make_float4(acc[i][0], acc[i][1], acc[i][2], acc[i][3]);
        if (!mode1) {
            v.x *= alpha; v.y *= alpha; v.z *= alpha; v.w *= alpha;
        } else if (piece == 0) {
            float4 d = *(const float4*)(Dmb + (size_t)tile * TSTRIDE + row * 64 + tx * 4);
            v = make_float4(d.x - v.x, d.y - v.y, d.z - v.z, d.w - v.w);
        } else {
            v = make_float4(-v.x, -v.y, -v.z, -v.w);
        }
        *(float4*)(Cp + row * 64 + tx * 4) = v;
    }
    __syncthreads();
}

// ---------------- one syrk chunk-job ----------------
__device__ __forceinline__ void syrk_job(
    const float* X, const float* yv, int q, int a0, int nc, int piece)
{
    extern __shared__ float s_dyn[];
    const int tid = threadIdx.x;
    const int pl = tid >> 4, c4 = (tid & 15) * 4;
    const int tx = tid & 15, ty = tid >> 4;
    int ti = 0, rem = q;
    while (rem >= NT - ti) { rem -= NT - ti; ti++; }
    const int tj = ti + rem;
    const int bm = ti * 64, bn = tj * 64;

    float4 va0, va1, vb0, vb1;
    auto aug4 = [&](int c0, int p) -> float4 {
        if (c0 < D_DIM) return *(const float4*)(X + (size_t)p * D_DIM + c0);
        float4 v = {0.f, 0.f, 0.f, 0.f};
        if (c0 == D_DIM) v.x = yv[p];
        return v;
    };
    auto ldg = [&](int ch) {
        const int p = (a0 + ch) * CH + pl;
        va0 = aug4(bm + c4, p);
        vb0 = aug4(bn + c4, p);
        va1 = aug4(bm + c4, p + 16);
        vb1 = aug4(bn + c4, p + 16);
    };
    auto sts = [&](int buf) {
        float* A = s_dyn + buf * SM_BUF;
        float* B = s_dyn + 2 * SM_BUF + buf * SM_BUF;
        *(float4*)(A + pl * 68 + c4) = va0;
        *(float4*)(B + pl * 68 + c4) = vb0;
        *(float4*)(A + (pl + 16) * 68 + c4) = va1;
        *(float4*)(B + (pl + 16) * 68 + c4) = vb1;
    };

    float acc[4][4] = {};
    ldg(0); sts(0);
    __syncthreads();
    for (int ch = 0; ch < nc; ch++) {
        const int buf = ch & 1;
        const bool more = (ch + 1 < nc);
        if (more) ldg(ch + 1);
        const float* A = s_dyn + buf * SM_BUF;
        const float* B = s_dyn + 2 * SM_BUF + buf * SM_BUF;
        #pragma unroll
        for (int kk = 0; kk < CH; kk++) {
            float4 a4 = *(const float4*)(A + kk * 68 + ty * 4);
            float4 b4 = *(const float4*)(B + kk * 68 + tx * 4);
            float a[4] = {a4.x, a4.y, a4.z, a4.w};
            float b[4] = {b4.x, b4.y, b4.z, b4.w};
            #pragma unroll
            for (int i = 0; i < 4; i++)
                #pragma unroll
                for (int j = 0; j < 4; j++)
                    acc[i][j] += a[i] * b[j];
        }
        if (more) {
            sts(buf ^ 1);
            __syncthreads();
        }
    }
    float* P = g_Spc + ((size_t)q * SPC + piece) * PSTRIDE;
    #pragma unroll
    for (int i = 0; i < 4; i++)
        *(float4*)(P + (ty * 4 + i) * 64 + tx * 4) =
            make_float4(acc[i][0], acc[i][1], acc[i][2], acc[i][3]);
    __syncthreads();
}

// ---------------- step descriptors ----------------
struct StepD { int a, b, dm, c; float alpha; };
__device__ __forceinline__ StepD get_step(int s) {
    if (s == 0) return {mWXA, mS,   -1, mT, 1.f};
    if (s == 1) return {mT,   mWXA, -1, mG, 1.f};
    if (s == 2) return {mWQT, mWKT, -1, mF, 1.f};
    const int l = (s - 3) >> 2, r = (s - 3) & 3;
    const int al = mA0 + l;
    if (r == 0) return {mF,   mG, -1, mT, 1.f};
    if (r == 1) return {mWVP, mT, -1, al, SCALE_A};
    if (r == 2) return {al,   mG, mG, mT2, 1.f};
    return {mT2, al, mT2, mG, 1.f};
}

// ================= the megakernel =================
__global__ __launch_bounds__(256, 2) void mega(
    const float* __restrict__ X,  const float* __restrict__ yv,
    const float* __restrict__ Xs, const float* __restrict__ Wx,
    const float* __restrict__ wy, const float* __restrict__ wo,
    const float* __restrict__ Wk, const float* __restrict__ Wq,
    const float* __restrict__ Wv, float* __restrict__ out)
{
    extern __shared__ float s_dyn[];
    const int tid  = threadIdx.x;
    const int cta  = blockIdx.x;
    const int gtid = cta * 256 + tid;
    const int lane = tid & 31;
    const int gw   = (cta << 3) + (tid >> 5);

    // -------- phase 0: operand conversion to tile layout --------
    for (int idx = gtid; idx < 4 * NTILES * PSTRIDE; idx += NCTA * 256) {
        const int m = idx / (NTILES * PSTRIDE);
        const int r4 = idx - m * (NTILES * PSTRIDE);
        const int t = r4 >> 12, e = r4 & 4095;
        const int r = (t / NT) * 64 + (e >> 6);
        const int cc = (t % NT) * 64 + (e & 63);
        const bool inb = (r < HID && cc < HID);
        float v = 0.f;
        if (m == 0) { if (r < HID) { if (cc < D_DIM) v = Wx[(size_t)r*D_DIM + cc];
                                     else if (cc == D_DIM) v = wy[r]; } }
        else if (m == 1) { if (inb) v = Wq[(size_t)cc*HID + r]; }
        else if (m == 2) { if (inb) v = Wk[(size_t)cc*HID + r]; }
        else             { if (inb) v = Wv[(size_t)r*HID + cc]; }
        g_M[m][(size_t)t * TSTRIDE + e] = v;
    }

    // -------- syrk --------
    {
        const int gs = ssch_start(cta), len = ssch_len(cta);
        const int t0 = gs / 256, a0 = gs % 256;
        const int n1 = (256 - a0 < len) ? (256 - a0) : len;
        syrk_job(X, yv, t0, a0, n1, cta - ssch_cta(t0 * 256));
        if (len > n1)
            syrk_job(X, yv, t0 + 1, 0, len - n1, 0);
    }
    gsync();

    // -------- S consolidation --------
    for (int idx = gtid; idx < SPAIR * PSTRIDE; idx += NCTA * 256) {
        const int q = idx >> 12, e = idx & 4095;
        const int np = np_syrk(q);
        float s = 0.f;
        for (int p = 0; p < np; p++) s += g_Spc[((size_t)q * SPC + p) * PSTRIDE + e];
        int ti = 0, rem = q;
        while (rem >= NT - ti) { rem -= NT - ti; ti++; }
        const int tj = ti + rem;
        const int m = e >> 6, n = e & 63;
        g_M[mS][(size_t)(ti * NT + tj) * TSTRIDE + e] = s;
        g_M[mS][(size_t)(tj * NT + ti) * TSTRIDE + n * 64 + m] = s;
    }
    gsync();

    // -------- 33 GEMM steps, each followed by piece consolidation --------
    const int ggs = gsch_start(cta), glen = gsch_len(cta);
    const int jt0 = ggs / KCHUNKS, ja0 = ggs % KCHUNKS;
    const int jn1 = (KCHUNKS - ja0 < glen) ? (KCHUNKS - ja0) : glen;
    const int p1 = cta - gsch_cta(jt0 * KCHUNKS);

    for (int s = 0; s < NSTEPS; s++) {
        const StepD st = get_step(s);
        const float* Ab = g_M[st.a];
        const float* Bb = g_M[st.b];
        const float* Db = (st.dm >= 0) ? g_M[st.dm] : nullptr;
        float* Cb = g_M[st.c];
        const int mode1 = (st.dm >= 0);
        gemm_job(Ab, Bb, Db, Cb, jt0, ja0, jn1, p1, st.alpha, mode1);
        if (glen > jn1)
            gemm_job(Ab, Bb, Db, Cb, jt0 + 1, 0, glen - jn1, 0, st.alpha, mode1);
        gsync();

        // consolidate output pieces into piece 0 (dense)
        for (int idx = gtid; idx < NTILES * (PSTRIDE / 4); idx += NCTA * 256) {
            const int t = idx >> 10;           // tile
            const int e4 = idx & 1023;         // float4 within tile
            const int np = np_gemm(t);
            float4* base = (float4*)(Cb + (size_t)t * TSTRIDE) + e4;
            float4 v = base[0];
            #pragma unroll
            for (int q2 = 1; q2 < NPIECE; q2++) {
                if (q2 < np) {
                    const float4 w = base[q2 * (PSTRIDE / 4)];
                    v.x += w.x; v.y += w.y; v.z += w.z; v.w += w.w;
                }
            }
            base[0] = v;
        }
        gsync();
    }

    // -------- u chain (A matrices dense now) --------
    for (int it = 0; it < 8; it++) {
        const float* Al = g_M[mA0 + (7 - it)];
        if (gw < HID) {
            const int j = gw, tj = j >> 6, jl = j & 63;
            float sacc = 0.f;
            #pragma unroll 2
            for (int i = lane; i < HID; i += 32) {
                const int t = (i >> 6) * NT + tj;
                const float av = Al[(size_t)t * TSTRIDE + (i & 63) * 64 + jl];
                const float uv = (it == 0) ? wo[i] : g_u[(it - 1) & 1][i];
                sacc += av * uv;
            }
            #pragma unroll
            for (int o = 16; o; o >>= 1) sacc += __shfl_xor_sync(0xFFFFFFFFu, sacc, o);
            if (lane == 0) {
                const float uj = (it == 0) ? wo[j] : g_u[(it - 1) & 1][j];
                g_u[it & 1][j] = uj + sacc;
            }
        }
        gsync();
    }

    // -------- d = Wx^T u --------
    if (gw < D_DIM) {
        const int j = gw;
        float sacc = 0.f;
        #pragma unroll 2
        for (int i = lane; i < HID; i += 32) sacc += Wx[(size_t)i * D_DIM + j] * g_u[1][i];
        #pragma unroll
        for (int o = 16; o; o >>= 1) sacc += __shfl_xor_sync(0xFFFFFFFFu, sacc, o);
        if (lane == 0) g_dv[j] = sacc;
    }
    gsync();

    // -------- out[k] = Xs[k,:] . d --------
    for (int r = gw; r < KTEST; r += NCTA * 8) {
        const float* row = Xs + (size_t)r * D_DIM;
        float sacc = 0.f;
        #pragma unroll 4
        for (int c2 = lane; c2 < D_DIM; c2 += 32) sacc += row[c2] * g_dv[c2];
        #pragma unroll
        for (int o = 16; o; o >>= 1) sacc += __shfl_xor_sync(0xFFFFFFFFu, sacc, o);
        if (lane == 0) out[r] = sacc;
    }
}

// ---------------- host ----------------
extern "C" void kernel_launch(void* const* d_in, const int* in_sizes, int n_in,
                              void* d_out, int out_size)
{
    const float* X  = (const float*)d_in[0];
    const float* y  = (const float*)d_in[1];
    const float* Xs = (const float*)d_in[2];
    const float* Wx = (const float*)d_in[3];
    const float* wy = (const float*)d_in[4];
    const float* wo = (const float*)d_in[5];
    const float* Wk = (const float*)d_in[6];
    const float* Wq = (const float*)d_in[7];
    const float* Wv = (const float*)d_in[8];
    float* out = (float*)d_out;

    mega<<<NCTA, 256, SMEM_BYTES>>>(X, y, Xs, Wx, wy, wo, Wk, Wq, Wv, out);
}